// round 1
// baseline (speedup 1.0000x reference)
#include <cuda_runtime.h>
#include <cstdint>

#define BATCH   16
#define NNODES  10000
#define HDIM    128
#define NEDGES  320000
#define NROWS   (BATCH * NNODES)      // 160000

// ---------------- scratch (device globals; no allocation allowed) ----------
__device__ int   g_counts[NNODES];
__device__ int   g_offsets[NNODES + 1];
__device__ int   g_cursor[NNODES];
__device__ int   g_csr[NEDGES];
__device__ float g_neighbor[(size_t)NROWS * HDIM];  // 81.92 MB
__device__ float g_h[(size_t)NROWS * HDIM];         // 81.92 MB

// ---------------- packed f32x2 helpers (FFMA2: full-rate fp32 on sm_103a) --
__device__ __forceinline__ void fma2(unsigned long long& d,
                                     unsigned long long a,
                                     unsigned long long b) {
    asm("fma.rn.f32x2 %0, %1, %2, %0;" : "+l"(d) : "l"(a), "l"(b));
}
__device__ __forceinline__ unsigned long long dup2(float a) {
    unsigned long long r;
    asm("mov.b64 %0, {%1, %1};" : "=l"(r) : "f"(a));
    return r;
}
__device__ __forceinline__ unsigned long long pack2(float x, float y) {
    unsigned long long r;
    asm("mov.b64 %0, {%1, %2};" : "=l"(r) : "f"(x), "f"(y));
    return r;
}
__device__ __forceinline__ float2 unpack2(unsigned long long v) {
    float2 r;
    asm("mov.b64 {%0, %1}, %2;" : "=f"(r.x), "=f"(r.y) : "l"(v));
    return r;
}

// ---------------- CSR build --------------------------------------------------
__global__ void zero_counts_k() {
    int i = blockIdx.x * blockDim.x + threadIdx.x;
    if (i < NNODES) g_counts[i] = 0;
}

__global__ void hist_k(const int* __restrict__ edge) {
    int e = blockIdx.x * blockDim.x + threadIdx.x;
    if (e < NEDGES) atomicAdd(&g_counts[edge[NEDGES + e]], 1);  // dst row
}

__global__ void scan_k() {
    __shared__ int part[1024];
    const int CH = 10;  // 1024*10 >= 10000
    int t = threadIdx.x;
    int local[CH];
    int s = 0;
#pragma unroll
    for (int i = 0; i < CH; i++) {
        int idx = t * CH + i;
        int v = (idx < NNODES) ? g_counts[idx] : 0;
        local[i] = s;
        s += v;
    }
    part[t] = s;
    __syncthreads();
    for (int off = 1; off < 1024; off <<= 1) {
        int v = (t >= off) ? part[t - off] : 0;
        __syncthreads();
        part[t] += v;
        __syncthreads();
    }
    int excl = (t == 0) ? 0 : part[t - 1];
#pragma unroll
    for (int i = 0; i < CH; i++) {
        int idx = t * CH + i;
        if (idx < NNODES) {
            int o = excl + local[i];
            g_offsets[idx] = o;
            g_cursor[idx]  = o;
        }
    }
    if (t == 1023) g_offsets[NNODES] = part[1023];
}

__global__ void scatter_k(const int* __restrict__ edge) {
    int e = blockIdx.x * blockDim.x + threadIdx.x;
    if (e < NEDGES) {
        int d = edge[NEDGES + e];
        int p = atomicAdd(&g_cursor[d], 1);
        g_csr[p] = edge[e];  // src index
    }
}

// ---------------- neighbor gather-sum (batch-major for L2 locality) ---------
__global__ __launch_bounds__(256)
void neighbor_k(const float* __restrict__ emb) {
    int warp_global = blockIdx.x * 8 + (threadIdx.x >> 5);
    if (warp_global >= NROWS) return;
    int b = warp_global / NNODES;   // batch-major: consecutive blocks -> same batch
    int n = warp_global - b * NNODES;
    int lane = threadIdx.x & 31;

    const float4* embB = (const float4*)(emb + (size_t)b * NNODES * HDIM);
    int beg = g_offsets[n];
    int end = g_offsets[n + 1];

    float4 acc = make_float4(0.f, 0.f, 0.f, 0.f);
    int i = beg;
    // unroll-4 for MLP
    for (; i + 4 <= end; i += 4) {
        int s0 = g_csr[i], s1 = g_csr[i + 1], s2 = g_csr[i + 2], s3 = g_csr[i + 3];
        float4 v0 = embB[s0 * 32 + lane];
        float4 v1 = embB[s1 * 32 + lane];
        float4 v2 = embB[s2 * 32 + lane];
        float4 v3 = embB[s3 * 32 + lane];
        acc.x += v0.x + v1.x + v2.x + v3.x;
        acc.y += v0.y + v1.y + v2.y + v3.y;
        acc.z += v0.z + v1.z + v2.z + v3.z;
        acc.w += v0.w + v1.w + v2.w + v3.w;
    }
    for (; i < end; i++) {
        float4 v = embB[g_csr[i] * 32 + lane];
        acc.x += v.x; acc.y += v.y; acc.z += v.z; acc.w += v.w;
    }
    ((float4*)g_neighbor)[(size_t)warp_global * 32 + lane] = acc;
}

// ---------------- fused SGEMM (f32x2 FFMA2), 128x128 tile, 8x8/thread -------
// FIRST=true : h = relu([neighbor | emb] @ W1 + b1)      (K=256, concat fused)
// FIRST=false: out = mask ? (h @ W2 + b2) : emb          (K=128, select fused)
template <bool FIRST>
__global__ __launch_bounds__(256, 2)
void gemm_k(const float* __restrict__ emb,
            const float* __restrict__ W,
            const float* __restrict__ bias,
            const int*   __restrict__ mask,
            float* __restrict__ outParam) {
    constexpr int KDIM   = FIRST ? 256 : 128;
    constexpr int NCHUNK = KDIM / 16;

    __shared__ float As[16][128];
    __shared__ float Bs[16][128];

    const float* A0   = FIRST ? g_neighbor : g_h;
    float*       outp = FIRST ? g_h : outParam;

    int rowBlock = blockIdx.x * 128;
    int t  = threadIdx.x;
    int tx = t & 15;
    int ty = t >> 4;
    int tx4 = tx * 4, ty4 = ty * 4;

    unsigned long long acc[8][4];
#pragma unroll
    for (int i = 0; i < 8; i++)
#pragma unroll
        for (int j = 0; j < 4; j++) acc[i][j] = 0ull;

    for (int ch = 0; ch < NCHUNK; ch++) {
        // --- load A tile (128 rows x 16 k), transposed into As[k][row] ---
        const float* Asrc = (FIRST && ch >= 8) ? emb : A0;
        int kb = (FIRST && ch >= 8) ? (ch - 8) * 16 : ch * 16;
#pragma unroll
        for (int l = 0; l < 2; l++) {
            int f   = t + l * 256;
            int row = f >> 2;
            int kq  = (f & 3) * 4;
            float4 v = *(const float4*)(Asrc + (size_t)(rowBlock + row) * HDIM + kb + kq);
            As[kq + 0][row] = v.x;
            As[kq + 1][row] = v.y;
            As[kq + 2][row] = v.z;
            As[kq + 3][row] = v.w;
        }
        // --- load W tile (16 k x 128 cols) ---
#pragma unroll
        for (int l = 0; l < 2; l++) {
            int f  = t + l * 256;
            int kk = f >> 5;
            int c4 = (f & 31) * 4;
            *(float4*)&Bs[kk][c4] =
                *(const float4*)(W + (size_t)(ch * 16 + kk) * 128 + c4);
        }
        __syncthreads();

#pragma unroll
        for (int k = 0; k < 16; k++) {
            float4 a0 = *(const float4*)&As[k][ty4];
            float4 a1 = *(const float4*)&As[k][ty4 + 64];
            float4 b0 = *(const float4*)&Bs[k][tx4];
            float4 b1 = *(const float4*)&Bs[k][tx4 + 64];
            unsigned long long av[8] = {dup2(a0.x), dup2(a0.y), dup2(a0.z), dup2(a0.w),
                                        dup2(a1.x), dup2(a1.y), dup2(a1.z), dup2(a1.w)};
            unsigned long long bv[4] = {pack2(b0.x, b0.y), pack2(b0.z, b0.w),
                                        pack2(b1.x, b1.y), pack2(b1.z, b1.w)};
#pragma unroll
            for (int i = 0; i < 8; i++)
#pragma unroll
                for (int j = 0; j < 4; j++) fma2(acc[i][j], av[i], bv[j]);
        }
        __syncthreads();
    }

    // --- epilogue ---
#pragma unroll
    for (int i = 0; i < 8; i++) {
        int r = rowBlock + ty4 + (i & 3) + ((i >> 2) * 64);
        bool doImpute = true;
        if (!FIRST) doImpute = (mask[r] != 0);
#pragma unroll
        for (int g = 0; g < 2; g++) {
            int c = tx4 + g * 64;
            float2 p0 = unpack2(acc[i][g * 2 + 0]);
            float2 p1 = unpack2(acc[i][g * 2 + 1]);
            float4 bb = *(const float4*)(bias + c);
            float4 v;
            v.x = p0.x + bb.x;
            v.y = p0.y + bb.y;
            v.z = p1.x + bb.z;
            v.w = p1.y + bb.w;
            if (FIRST) {
                v.x = fmaxf(v.x, 0.f);
                v.y = fmaxf(v.y, 0.f);
                v.z = fmaxf(v.z, 0.f);
                v.w = fmaxf(v.w, 0.f);
            } else if (!doImpute) {
                v = *(const float4*)(emb + (size_t)r * HDIM + c);
            }
            *(float4*)(outp + (size_t)r * HDIM + c) = v;
        }
    }
}

// ---------------- launch -----------------------------------------------------
extern "C" void kernel_launch(void* const* d_in, const int* in_sizes, int n_in,
                              void* d_out, int out_size) {
    const float* emb  = (const float*)d_in[0];
    const int*   mask = (const int*)d_in[1];
    const int*   edge = (const int*)d_in[2];
    const float* W1   = (const float*)d_in[3];
    const float* b1   = (const float*)d_in[4];
    const float* W2   = (const float*)d_in[5];
    const float* b2   = (const float*)d_in[6];
    float*       out  = (float*)d_out;

    zero_counts_k<<<(NNODES + 255) / 256, 256>>>();
    hist_k<<<(NEDGES + 255) / 256, 256>>>(edge);
    scan_k<<<1, 1024>>>();
    scatter_k<<<(NEDGES + 255) / 256, 256>>>(edge);
    neighbor_k<<<NROWS / 8, 256>>>(emb);
    gemm_k<true><<<NROWS / 128, 256>>>(emb, W1, b1, nullptr, nullptr);
    gemm_k<false><<<NROWS / 128, 256>>>(emb, W2, b2, mask, out);
}

// round 3
// speedup vs baseline: 1.1709x; 1.1709x over previous
#include <cuda_runtime.h>
#include <cuda_bf16.h>
#include <cstdint>

#define BATCH   16
#define NNODES  10000
#define HDIM    128
#define NEDGES  320000
#define NROWS   (BATCH * NNODES)      // 160000

// ---------------- scratch (device globals; no allocation allowed) ----------
__device__ int   g_counts[NNODES];
__device__ int   g_offsets[NNODES + 1];
__device__ int   g_cursor[NNODES];
__device__ int   g_csr[NEDGES];
__device__ float g_neighbor[(size_t)NROWS * HDIM];       // 81.9 MB
__device__ __nv_bfloat16 g_h_hi[(size_t)NROWS * HDIM];   // 41 MB
__device__ __nv_bfloat16 g_h_lo[(size_t)NROWS * HDIM];   // 41 MB
// weights in native [K][N=128] row-major, bf16 hi/lo split
__device__ __nv_bfloat16 g_w1_hi[256 * 128];
__device__ __nv_bfloat16 g_w1_lo[256 * 128];
__device__ __nv_bfloat16 g_w2_hi[128 * 128];
__device__ __nv_bfloat16 g_w2_lo[128 * 128];

// ---------------- helpers -----------------------------------------------------
__device__ __forceinline__ uint32_t smem_u32(const void* p) {
    uint32_t a;
    asm("{ .reg .u64 t; cvta.to.shared.u64 t, %1; cvt.u32.u64 %0, t; }"
        : "=r"(a) : "l"(p));
    return a;
}
__device__ __forceinline__ void split2(float x0, float x1,
                                       uint32_t& hi, uint32_t& lo) {
    __nv_bfloat162 h = __float22bfloat162_rn(make_float2(x0, x1));
    __nv_bfloat162 l = __float22bfloat162_rn(
        make_float2(x0 - __bfloat162float(h.x), x1 - __bfloat162float(h.y)));
    hi = *(uint32_t*)&h;
    lo = *(uint32_t*)&l;
}
__device__ __forceinline__ void ldsm4(uint32_t* r, uint32_t a) {
    asm volatile("ldmatrix.sync.aligned.m8n8.x4.shared.b16 {%0,%1,%2,%3}, [%4];"
                 : "=r"(r[0]), "=r"(r[1]), "=r"(r[2]), "=r"(r[3]) : "r"(a));
}
__device__ __forceinline__ void ldsm4t(uint32_t* r, uint32_t a) {
    asm volatile("ldmatrix.sync.aligned.m8n8.x4.trans.shared.b16 {%0,%1,%2,%3}, [%4];"
                 : "=r"(r[0]), "=r"(r[1]), "=r"(r[2]), "=r"(r[3]) : "r"(a));
}
__device__ __forceinline__ void mma16816(float* c, const uint32_t* a,
                                         uint32_t b0, uint32_t b1) {
    asm volatile(
        "mma.sync.aligned.m16n8k16.row.col.f32.bf16.bf16.f32 "
        "{%0,%1,%2,%3}, {%4,%5,%6,%7}, {%8,%9}, {%0,%1,%2,%3};"
        : "+f"(c[0]), "+f"(c[1]), "+f"(c[2]), "+f"(c[3])
        : "r"(a[0]), "r"(a[1]), "r"(a[2]), "r"(a[3]), "r"(b0), "r"(b1));
}

// ---------------- CSR build ----------------------------------------------------
__global__ void zero_counts_k() {
    int i = blockIdx.x * blockDim.x + threadIdx.x;
    if (i < NNODES) g_counts[i] = 0;
}
__global__ void hist_k(const int* __restrict__ edge) {
    int e = blockIdx.x * blockDim.x + threadIdx.x;
    if (e < NEDGES) atomicAdd(&g_counts[edge[NEDGES + e]], 1);
}
__global__ void scan_k() {
    __shared__ int part[1024];
    const int CH = 10;
    int t = threadIdx.x;
    int local[CH];
    int s = 0;
#pragma unroll
    for (int i = 0; i < CH; i++) {
        int idx = t * CH + i;
        int v = (idx < NNODES) ? g_counts[idx] : 0;
        local[i] = s;
        s += v;
    }
    part[t] = s;
    __syncthreads();
    for (int off = 1; off < 1024; off <<= 1) {
        int v = (t >= off) ? part[t - off] : 0;
        __syncthreads();
        part[t] += v;
        __syncthreads();
    }
    int excl = (t == 0) ? 0 : part[t - 1];
#pragma unroll
    for (int i = 0; i < CH; i++) {
        int idx = t * CH + i;
        if (idx < NNODES) {
            int o = excl + local[i];
            g_offsets[idx] = o;
            g_cursor[idx]  = o;
        }
    }
    if (t == 1023) g_offsets[NNODES] = part[1023];
}
__global__ void scatter_k(const int* __restrict__ edge) {
    int e = blockIdx.x * blockDim.x + threadIdx.x;
    if (e < NEDGES) {
        int d = edge[NEDGES + e];
        int p = atomicAdd(&g_cursor[d], 1);
        g_csr[p] = edge[e];
    }
}

// ---------------- neighbor gather-sum (batch-major, L2 resident) --------------
__global__ __launch_bounds__(256)
void neighbor_k(const float* __restrict__ emb) {
    int warp_global = blockIdx.x * 8 + (threadIdx.x >> 5);
    if (warp_global >= NROWS) return;
    int b = warp_global / NNODES;
    int n = warp_global - b * NNODES;
    int lane = threadIdx.x & 31;

    const float4* embB = (const float4*)(emb + (size_t)b * NNODES * HDIM);
    int beg = g_offsets[n];
    int end = g_offsets[n + 1];

    float4 acc = make_float4(0.f, 0.f, 0.f, 0.f);
    int i = beg;
    for (; i + 4 <= end; i += 4) {
        int s0 = g_csr[i], s1 = g_csr[i + 1], s2 = g_csr[i + 2], s3 = g_csr[i + 3];
        float4 v0 = embB[s0 * 32 + lane];
        float4 v1 = embB[s1 * 32 + lane];
        float4 v2 = embB[s2 * 32 + lane];
        float4 v3 = embB[s3 * 32 + lane];
        acc.x += v0.x + v1.x + v2.x + v3.x;
        acc.y += v0.y + v1.y + v2.y + v3.y;
        acc.z += v0.z + v1.z + v2.z + v3.z;
        acc.w += v0.w + v1.w + v2.w + v3.w;
    }
    for (; i < end; i++) {
        float4 v = embB[g_csr[i] * 32 + lane];
        acc.x += v.x; acc.y += v.y; acc.z += v.z; acc.w += v.w;
    }
    ((float4*)g_neighbor)[(size_t)warp_global * 32 + lane] = acc;
}

// ---------------- weight bf16 hi/lo split (layout preserved [K][128]) ---------
__global__ void wconv_k(const float* __restrict__ W, __nv_bfloat16* oh,
                        __nv_bfloat16* ol, int total) {
    int i = blockIdx.x * blockDim.x + threadIdx.x;
    if (i < total) {
        float x = W[i];
        __nv_bfloat16 h = __float2bfloat16_rn(x);
        oh[i] = h;
        ol[i] = __float2bfloat16_rn(x - __bfloat162float(h));
    }
}

// ---------------- warp-MMA GEMM, bf16 3-pass hi/lo split ----------------------
// FIRST: h = relu([neighbor|emb] @ W1 + b1)  -> g_h hi/lo   (K=256)
// else : out = mask ? (h @ W2 + b2) : emb                    (K=128)
template <bool FIRST>
__global__ __launch_bounds__(256)
void mma_gemm_k(const float* __restrict__ bias, const int* __restrict__ mask,
                const float* __restrict__ emb, float* __restrict__ outp) {
    constexpr int KDIM = FIRST ? 256 : 128;
    constexpr int NCH  = KDIM / 64;          // 64-wide K chunks

    extern __shared__ __align__(128) char smem[];
    char* sBhi = smem;                        // [KDIM][128 bf16] swizzled
    char* sBlo = sBhi + KDIM * 256;
    char* sA   = sBlo + KDIM * 256;           // 2 bufs x (hi 16KB | lo 16KB)

    int tid  = threadIdx.x;
    int lane = tid & 31;
    int wid  = tid >> 5;
    int wm   = wid & 3;                       // 4 warps over M (32 rows each)
    int wn   = wid >> 2;                      // 2 warps over N (64 cols each)
    int rowBase = blockIdx.x * 128;

    // --- B resident (swizzled): offset(k,c16) = k*256 + ((c^ (k&7))<<4) ---
    const __nv_bfloat16* BH = FIRST ? g_w1_hi : g_w2_hi;
    const __nv_bfloat16* BL = FIRST ? g_w1_lo : g_w2_lo;
    for (int idx = tid; idx < KDIM * 16; idx += 256) {
        int k = idx >> 4, c = idx & 15;
        uint32_t off = (uint32_t)(k * 256 + ((c ^ (k & 7)) << 4));
        *(uint4*)(sBhi + off) = *(const uint4*)(BH + (size_t)k * 128 + c * 8);
        *(uint4*)(sBlo + off) = *(const uint4*)(BL + (size_t)k * 128 + c * 8);
    }

    float acc[2][8][4];
#pragma unroll
    for (int mi = 0; mi < 2; mi++)
#pragma unroll
        for (int n8 = 0; n8 < 8; n8++)
#pragma unroll
            for (int q = 0; q < 4; q++) acc[mi][n8][q] = 0.f;

    // --- A staging lambda-ish: chunk ch -> buffer buf ---
    // A smem row = 64 bf16 = 8 chunks of 16B; offset(r,c)=r*128+((c^(r&7))<<4)
    auto stage = [&](int ch, int buf) {
        char* dH = sA + buf * 32768;
        char* dL = dH + 16384;
        int kb = ch * 64;
#pragma unroll
        for (int it = 0; it < 4; it++) {
            int idx = it * 256 + tid;        // 1024 chunks
            int r = idx >> 3, c = idx & 7;
            uint32_t off = (uint32_t)(r * 128 + ((c ^ (r & 7)) << 4));
            size_t row = (size_t)(rowBase + r);
            if (FIRST) {
                int g0 = kb + c * 8;
                const float* src = (g0 < 128)
                    ? (g_neighbor + row * 128 + g0)
                    : (emb + row * 128 + (g0 - 128));
                float4 v0 = *(const float4*)src;
                float4 v1 = *(const float4*)(src + 4);
                uint32_t h[4], l[4];
                split2(v0.x, v0.y, h[0], l[0]);
                split2(v0.z, v0.w, h[1], l[1]);
                split2(v1.x, v1.y, h[2], l[2]);
                split2(v1.z, v1.w, h[3], l[3]);
                *(uint4*)(dH + off) = make_uint4(h[0], h[1], h[2], h[3]);
                *(uint4*)(dL + off) = make_uint4(l[0], l[1], l[2], l[3]);
            } else {
                *(uint4*)(dH + off) =
                    *(const uint4*)(g_h_hi + row * 128 + kb + c * 8);
                *(uint4*)(dL + off) =
                    *(const uint4*)(g_h_lo + row * 128 + kb + c * 8);
            }
        }
    };

    uint32_t sA_u   = smem_u32(sA);
    uint32_t sBhi_u = smem_u32(sBhi);
    uint32_t sBlo_u = smem_u32(sBlo);

    stage(0, 0);
    __syncthreads();

    for (int ch = 0; ch < NCH; ch++) {
        if (ch + 1 < NCH) stage(ch + 1, (ch + 1) & 1);

        uint32_t aHiB = sA_u + (uint32_t)((ch & 1) * 32768);
        uint32_t aLoB = aHiB + 16384;

#pragma unroll
        for (int kk = 0; kk < 4; kk++) {
            int kB = ch * 64 + kk * 16;
            uint32_t aH[2][4], aL[2][4], bF[4][4];
#pragma unroll
            for (int mi = 0; mi < 2; mi++) {
                int r = wm * 32 + mi * 16 + (lane & 15);
                int c = kk * 2 + (lane >> 4);
                uint32_t off = (uint32_t)(r * 128 + ((c ^ (r & 7)) << 4));
                ldsm4(aH[mi], aHiB + off);
                ldsm4(aL[mi], aLoB + off);
            }
            uint32_t boff[4];
#pragma unroll
            for (int q = 0; q < 4; q++) {
                int k  = kB + (lane & 15);
                int n0 = wn * 64 + q * 16 + ((lane >> 4) << 3);
                int c  = n0 >> 3;
                boff[q] = (uint32_t)(k * 256 + ((c ^ (k & 7)) << 4));
                ldsm4t(bF[q], sBhi_u + boff[q]);
            }
#pragma unroll
            for (int mi = 0; mi < 2; mi++)
#pragma unroll
                for (int n8 = 0; n8 < 8; n8++)
                    mma16816(acc[mi][n8], aH[mi],
                             bF[n8 >> 1][(n8 & 1) * 2], bF[n8 >> 1][(n8 & 1) * 2 + 1]);
#pragma unroll
            for (int mi = 0; mi < 2; mi++)
#pragma unroll
                for (int n8 = 0; n8 < 8; n8++)
                    mma16816(acc[mi][n8], aL[mi],
                             bF[n8 >> 1][(n8 & 1) * 2], bF[n8 >> 1][(n8 & 1) * 2 + 1]);
#pragma unroll
            for (int q = 0; q < 4; q++) ldsm4t(bF[q], sBlo_u + boff[q]);
#pragma unroll
            for (int mi = 0; mi < 2; mi++)
#pragma unroll
                for (int n8 = 0; n8 < 8; n8++)
                    mma16816(acc[mi][n8], aH[mi],
                             bF[n8 >> 1][(n8 & 1) * 2], bF[n8 >> 1][(n8 & 1) * 2 + 1]);
        }
        __syncthreads();
    }

    // --- epilogue ---
    int g = lane >> 2, tig = lane & 3;
#pragma unroll
    for (int mi = 0; mi < 2; mi++) {
#pragma unroll
        for (int half = 0; half < 2; half++) {
            int r = rowBase + wm * 32 + mi * 16 + g + half * 8;
            bool doImp = true;
            if (!FIRST) doImp = (mask[r] != 0);
#pragma unroll
            for (int n8 = 0; n8 < 8; n8++) {
                int cidx = wn * 64 + n8 * 8 + tig * 2;
                float x0 = acc[mi][n8][half * 2 + 0] + __ldg(bias + cidx);
                float x1 = acc[mi][n8][half * 2 + 1] + __ldg(bias + cidx + 1);
                if (FIRST) {
                    x0 = fmaxf(x0, 0.f);
                    x1 = fmaxf(x1, 0.f);
                    uint32_t hh, ll;
                    split2(x0, x1, hh, ll);
                    *(uint32_t*)(g_h_hi + (size_t)r * 128 + cidx) = hh;
                    *(uint32_t*)(g_h_lo + (size_t)r * 128 + cidx) = ll;
                } else {
                    float2 v = make_float2(x0, x1);
                    if (!doImp)
                        v = *(const float2*)(emb + (size_t)r * 128 + cidx);
                    *(float2*)(outp + (size_t)r * 128 + cidx) = v;
                }
            }
        }
    }
}

// ---------------- launch -------------------------------------------------------
extern "C" void kernel_launch(void* const* d_in, const int* in_sizes, int n_in,
                              void* d_out, int out_size) {
    const float* emb  = (const float*)d_in[0];
    const int*   mask = (const int*)d_in[1];
    const int*   edge = (const int*)d_in[2];
    const float* W1   = (const float*)d_in[3];
    const float* b1   = (const float*)d_in[4];
    const float* W2   = (const float*)d_in[5];
    const float* b2   = (const float*)d_in[6];
    float*       out  = (float*)d_out;

    const int SMEM1 = 256 * 256 * 2 + 65536;   // 196608
    const int SMEM2 = 128 * 256 * 2 + 65536;   // 131072
    cudaFuncSetAttribute(mma_gemm_k<true>,
                         cudaFuncAttributeMaxDynamicSharedMemorySize, SMEM1);
    cudaFuncSetAttribute(mma_gemm_k<false>,
                         cudaFuncAttributeMaxDynamicSharedMemorySize, SMEM2);

    // CSR build
    zero_counts_k<<<(NNODES + 255) / 256, 256>>>();
    hist_k<<<(NEDGES + 255) / 256, 256>>>(edge);
    scan_k<<<1, 1024>>>();
    scatter_k<<<(NEDGES + 255) / 256, 256>>>(edge);

    // weight splits (tiny)
    __nv_bfloat16 *w1h, *w1l, *w2h, *w2l;
    cudaGetSymbolAddress((void**)&w1h, g_w1_hi);
    cudaGetSymbolAddress((void**)&w1l, g_w1_lo);
    cudaGetSymbolAddress((void**)&w2h, g_w2_hi);
    cudaGetSymbolAddress((void**)&w2l, g_w2_lo);
    wconv_k<<<128, 256>>>(W1, w1h, w1l, 256 * 128);
    wconv_k<<<64, 256>>>(W2, w2h, w2l, 128 * 128);

    // neighbor gather
    neighbor_k<<<NROWS / 8, 256>>>(emb);

    // tensor-core GEMMs
    mma_gemm_k<true><<<NROWS / 128, 256, SMEM1>>>(b1, nullptr, emb, nullptr);
    mma_gemm_k<false><<<NROWS / 128, 256, SMEM2>>>(b2, mask, emb, out);
}

// round 4
// speedup vs baseline: 1.5088x; 1.2886x over previous
#include <cuda_runtime.h>
#include <cuda_bf16.h>
#include <cuda_fp16.h>
#include <cstdint>

#define BATCH   16
#define NNODES  10000
#define HDIM    128
#define NEDGES  320000
#define NROWS   (BATCH * NNODES)      // 160000
#define NTILES  (NROWS / 128)         // 1250

// ---------------- scratch (device globals; no allocation allowed) ----------
__device__ int    g_counts[NNODES];
__device__ int    g_offsets[NNODES + 1];
__device__ int    g_cursor[NNODES];
__device__ int    g_csr[NEDGES];
__device__ __half g_emb16[(size_t)NROWS * HDIM];          // 41 MB fp16 copy
__device__ __nv_bfloat16 g_nbr_hi[(size_t)NROWS * HDIM];  // 41 MB
__device__ __nv_bfloat16 g_nbr_lo[(size_t)NROWS * HDIM];  // 41 MB
// weights native [K][N=128] row-major, bf16 hi/lo split
__device__ __nv_bfloat16 g_w1_hi[256 * 128];
__device__ __nv_bfloat16 g_w1_lo[256 * 128];
__device__ __nv_bfloat16 g_w2_hi[128 * 128];
__device__ __nv_bfloat16 g_w2_lo[128 * 128];

// ---------------- helpers -----------------------------------------------------
__device__ __forceinline__ uint32_t smem_u32(const void* p) {
    uint32_t a;
    asm("{ .reg .u64 t; cvta.to.shared.u64 t, %1; cvt.u32.u64 %0, t; }"
        : "=r"(a) : "l"(p));
    return a;
}
__device__ __forceinline__ void split2(float x0, float x1,
                                       uint32_t& hi, uint32_t& lo) {
    __nv_bfloat162 h = __float22bfloat162_rn(make_float2(x0, x1));
    __nv_bfloat162 l = __float22bfloat162_rn(
        make_float2(x0 - __bfloat162float(h.x), x1 - __bfloat162float(h.y)));
    hi = *(uint32_t*)&h;
    lo = *(uint32_t*)&l;
}
__device__ __forceinline__ void ldsm4(uint32_t* r, uint32_t a) {
    asm volatile("ldmatrix.sync.aligned.m8n8.x4.shared.b16 {%0,%1,%2,%3}, [%4];"
                 : "=r"(r[0]), "=r"(r[1]), "=r"(r[2]), "=r"(r[3]) : "r"(a));
}
__device__ __forceinline__ void ldsm4t(uint32_t* r, uint32_t a) {
    asm volatile("ldmatrix.sync.aligned.m8n8.x4.trans.shared.b16 {%0,%1,%2,%3}, [%4];"
                 : "=r"(r[0]), "=r"(r[1]), "=r"(r[2]), "=r"(r[3]) : "r"(a));
}
__device__ __forceinline__ void mma16816(float* c, const uint32_t* a,
                                         uint32_t b0, uint32_t b1) {
    asm volatile(
        "mma.sync.aligned.m16n8k16.row.col.f32.bf16.bf16.f32 "
        "{%0,%1,%2,%3}, {%4,%5,%6,%7}, {%8,%9}, {%0,%1,%2,%3};"
        : "+f"(c[0]), "+f"(c[1]), "+f"(c[2]), "+f"(c[3])
        : "r"(a[0]), "r"(a[1]), "r"(a[2]), "r"(a[3]), "r"(b0), "r"(b1));
}

// ---------------- CSR build ----------------------------------------------------
__global__ void zero_counts_k() {
    int i = blockIdx.x * blockDim.x + threadIdx.x;
    if (i < NNODES) g_counts[i] = 0;
}
__global__ void hist_k(const int* __restrict__ edge) {
    int e = blockIdx.x * blockDim.x + threadIdx.x;
    if (e < NEDGES) atomicAdd(&g_counts[edge[NEDGES + e]], 1);
}
__global__ void scan_k() {
    __shared__ int part[1024];
    const int CH = 10;
    int t = threadIdx.x;
    int local[CH];
    int s = 0;
#pragma unroll
    for (int i = 0; i < CH; i++) {
        int idx = t * CH + i;
        int v = (idx < NNODES) ? g_counts[idx] : 0;
        local[i] = s;
        s += v;
    }
    part[t] = s;
    __syncthreads();
    for (int off = 1; off < 1024; off <<= 1) {
        int v = (t >= off) ? part[t - off] : 0;
        __syncthreads();
        part[t] += v;
        __syncthreads();
    }
    int excl = (t == 0) ? 0 : part[t - 1];
#pragma unroll
    for (int i = 0; i < CH; i++) {
        int idx = t * CH + i;
        if (idx < NNODES) {
            int o = excl + local[i];
            g_offsets[idx] = o;
            g_cursor[idx]  = o;
        }
    }
    if (t == 1023) g_offsets[NNODES] = part[1023];
}
__global__ void scatter_k(const int* __restrict__ edge) {
    int e = blockIdx.x * blockDim.x + threadIdx.x;
    if (e < NEDGES) {
        int d = edge[NEDGES + e];
        int p = atomicAdd(&g_cursor[d], 1);
        g_csr[p] = edge[e];
    }
}

// ---------------- emb fp32 -> fp16 copy ---------------------------------------
__global__ __launch_bounds__(256)
void econv16_k(const float* __restrict__ emb) {
    size_t i8 = (size_t)blockIdx.x * 256 + threadIdx.x;   // one 8-elt group
    const float4* s = (const float4*)(emb) + i8 * 2;
    float4 a = s[0], b = s[1];
    __half2 h0 = __float22half2_rn(make_float2(a.x, a.y));
    __half2 h1 = __float22half2_rn(make_float2(a.z, a.w));
    __half2 h2 = __float22half2_rn(make_float2(b.x, b.y));
    __half2 h3 = __float22half2_rn(make_float2(b.z, b.w));
    uint4 o;
    o.x = *(uint32_t*)&h0; o.y = *(uint32_t*)&h1;
    o.z = *(uint32_t*)&h2; o.w = *(uint32_t*)&h3;
    *((uint4*)g_emb16 + i8) = o;
}

// ---------------- neighbor gather-sum: fp16 reads, fp32 acc, bf16 hi/lo out ---
__global__ __launch_bounds__(256)
void neighbor_k() {
    int warp_global = blockIdx.x * 8 + (threadIdx.x >> 5);
    if (warp_global >= NROWS) return;
    int b = warp_global / NNODES;
    int n = warp_global - b * NNODES;
    int lane = threadIdx.x & 31;

    const __half* embB = g_emb16 + (size_t)b * NNODES * HDIM;
    int beg = g_offsets[n];
    int end = g_offsets[n + 1];

    float4 acc = make_float4(0.f, 0.f, 0.f, 0.f);
    int i = beg;
    for (; i + 4 <= end; i += 4) {
        int s0 = g_csr[i], s1 = g_csr[i + 1], s2 = g_csr[i + 2], s3 = g_csr[i + 3];
        uint2 p0 = *(const uint2*)(embB + (size_t)s0 * 128 + lane * 4);
        uint2 p1 = *(const uint2*)(embB + (size_t)s1 * 128 + lane * 4);
        uint2 p2 = *(const uint2*)(embB + (size_t)s2 * 128 + lane * 4);
        uint2 p3 = *(const uint2*)(embB + (size_t)s3 * 128 + lane * 4);
#pragma unroll
        for (int q = 0; q < 4; q++) {
            uint2 p = (q == 0) ? p0 : (q == 1) ? p1 : (q == 2) ? p2 : p3;
            float2 f0 = __half22float2(*(__half2*)&p.x);
            float2 f1 = __half22float2(*(__half2*)&p.y);
            acc.x += f0.x; acc.y += f0.y; acc.z += f1.x; acc.w += f1.y;
        }
    }
    for (; i < end; i++) {
        uint2 p = *(const uint2*)(embB + (size_t)g_csr[i] * 128 + lane * 4);
        float2 f0 = __half22float2(*(__half2*)&p.x);
        float2 f1 = __half22float2(*(__half2*)&p.y);
        acc.x += f0.x; acc.y += f0.y; acc.z += f1.x; acc.w += f1.y;
    }
    uint32_t h0, l0, h1, l1;
    split2(acc.x, acc.y, h0, l0);
    split2(acc.z, acc.w, h1, l1);
    size_t o = (size_t)warp_global * 128 + lane * 4;
    *(uint2*)(g_nbr_hi + o) = make_uint2(h0, h1);
    *(uint2*)(g_nbr_lo + o) = make_uint2(l0, l1);
}

// ---------------- weight bf16 hi/lo split (layout preserved [K][128]) ---------
__global__ void wconv_k(const float* __restrict__ W, __nv_bfloat16* oh,
                        __nv_bfloat16* ol, int total) {
    int i = blockIdx.x * blockDim.x + threadIdx.x;
    if (i < total) {
        float x = W[i];
        __nv_bfloat16 h = __float2bfloat16_rn(x);
        oh[i] = h;
        ol[i] = __float2bfloat16_rn(x - __bfloat162float(h));
    }
}

// ---------------- fused GEMM1+GEMM2, persistent, 3-pass bf16 hi/lo ------------
// smem map (192KB dynamic):
//   [0, 64K)      W1hi  -> after GEMM1: h chunk bufs (c0hi@0, c0lo@16K, c1hi@32K, c1lo@48K)
//   [64K, 128K)   W1lo  -> after GEMM1: W2hi@64K, W2lo@96K
//   [128K, 192K)  A staging: buf0 hi@128K lo@+16K, buf1 hi@160K lo@+16K
#define SM_W1    0
#define SM_W2HI  65536
#define SM_W2LO  98304
#define SM_STAGE 131072
#define SMEM_FUSED 196608

__global__ __launch_bounds__(256, 1)
void fused_k(const float* __restrict__ bias1, const float* __restrict__ bias2,
             const int* __restrict__ mask, const float* __restrict__ emb32,
             float* __restrict__ outp) {
    extern __shared__ __align__(128) char smem[];
    int tid  = threadIdx.x;
    int lane = tid & 31;
    int wid  = tid >> 5;
    int wm   = wid & 3;
    int wn   = wid >> 2;
    int g    = lane >> 2, tig = lane & 3;
    uint32_t sb = smem_u32(smem);

    float acc[2][8][4];

    for (int tile = blockIdx.x; tile < NTILES; tile += gridDim.x) {
        int rowBase = tile * 128;

        // ---- load W1 hi/lo into [0,128K) swizzled ----
#pragma unroll
        for (int i = 0; i < 16; i++) {
            int idx = i * 256 + tid;                 // 4096 chunks
            int k = idx >> 4, c = idx & 15;
            uint32_t off = (uint32_t)(k * 256 + ((c ^ (k & 7)) << 4));
            *(uint4*)(smem + SM_W1 + off) =
                *(const uint4*)(g_w1_hi + (size_t)k * 128 + c * 8);
            *(uint4*)(smem + 65536 + off) =
                *(const uint4*)(g_w1_lo + (size_t)k * 128 + c * 8);
        }

#pragma unroll
        for (int mi = 0; mi < 2; mi++)
#pragma unroll
            for (int n8 = 0; n8 < 8; n8++)
#pragma unroll
                for (int q = 0; q < 4; q++) acc[mi][n8][q] = 0.f;

        // ---- A staging: chunk ch -> buf ----
        auto stage = [&](int ch, int buf) {
            char* dH = smem + SM_STAGE + buf * 32768;
            char* dL = dH + 16384;
#pragma unroll
            for (int it = 0; it < 4; it++) {
                int idx = it * 256 + tid;            // 1024 chunks
                int r = idx >> 3, c = idx & 7;
                uint32_t off = (uint32_t)(r * 128 + ((c ^ (r & 7)) << 4));
                size_t row = (size_t)(rowBase + r);
                if (ch < 2) {
                    int g0 = ch * 64 + c * 8;
                    *(uint4*)(dH + off) = *(const uint4*)(g_nbr_hi + row * 128 + g0);
                    *(uint4*)(dL + off) = *(const uint4*)(g_nbr_lo + row * 128 + g0);
                } else {
                    int g0 = (ch - 2) * 64 + c * 8;
                    uint4 p = *(const uint4*)(g_emb16 + row * 128 + g0);
                    float2 f0 = __half22float2(*(__half2*)&p.x);
                    float2 f1 = __half22float2(*(__half2*)&p.y);
                    float2 f2 = __half22float2(*(__half2*)&p.z);
                    float2 f3 = __half22float2(*(__half2*)&p.w);
                    uint4 vh, vl;
                    split2(f0.x, f0.y, vh.x, vl.x);
                    split2(f1.x, f1.y, vh.y, vl.y);
                    split2(f2.x, f2.y, vh.z, vl.z);
                    split2(f3.x, f3.y, vh.w, vl.w);
                    *(uint4*)(dH + off) = vh;
                    *(uint4*)(dL + off) = vl;
                }
            }
        };

        // ---- 3-pass MMA block for one kk of one chunk ----
        auto mma_block = [&](uint32_t aHiB, uint32_t aLoB, uint32_t bHiB,
                             uint32_t bLoB, int kk, int kAbs) {
            uint32_t aH[2][4], aL[2][4], bF[4][4], boff[4];
#pragma unroll
            for (int mi = 0; mi < 2; mi++) {
                int r = wm * 32 + mi * 16 + (lane & 15);
                int c = kk * 2 + (lane >> 4);
                uint32_t off = (uint32_t)(r * 128 + ((c ^ (r & 7)) << 4));
                ldsm4(aH[mi], aHiB + off);
                ldsm4(aL[mi], aLoB + off);
            }
#pragma unroll
            for (int q = 0; q < 4; q++) {
                int k  = kAbs + (lane & 15);
                int c  = (wn * 64 + q * 16 + ((lane >> 4) << 3)) >> 3;
                boff[q] = (uint32_t)(k * 256 + ((c ^ (k & 7)) << 4));
                ldsm4t(bF[q], bHiB + boff[q]);
            }
#pragma unroll
            for (int mi = 0; mi < 2; mi++)
#pragma unroll
                for (int n8 = 0; n8 < 8; n8++)
                    mma16816(acc[mi][n8], aH[mi],
                             bF[n8 >> 1][(n8 & 1) * 2], bF[n8 >> 1][(n8 & 1) * 2 + 1]);
#pragma unroll
            for (int mi = 0; mi < 2; mi++)
#pragma unroll
                for (int n8 = 0; n8 < 8; n8++)
                    mma16816(acc[mi][n8], aL[mi],
                             bF[n8 >> 1][(n8 & 1) * 2], bF[n8 >> 1][(n8 & 1) * 2 + 1]);
#pragma unroll
            for (int q = 0; q < 4; q++) ldsm4t(bF[q], bLoB + boff[q]);
#pragma unroll
            for (int mi = 0; mi < 2; mi++)
#pragma unroll
                for (int n8 = 0; n8 < 8; n8++)
                    mma16816(acc[mi][n8], aH[mi],
                             bF[n8 >> 1][(n8 & 1) * 2], bF[n8 >> 1][(n8 & 1) * 2 + 1]);
        };

        stage(0, 0);
        __syncthreads();

        // ---- GEMM1: K=256 in 4 chunks ----
        for (int ch = 0; ch < 4; ch++) {
            if (ch + 1 < 4) stage(ch + 1, (ch + 1) & 1);
            uint32_t aHiB = sb + SM_STAGE + (uint32_t)((ch & 1) * 32768);
            uint32_t aLoB = aHiB + 16384;
#pragma unroll
            for (int kk = 0; kk < 4; kk++)
                mma_block(aHiB, aLoB, sb + SM_W1, sb + 65536, kk,
                          ch * 64 + kk * 16);
            __syncthreads();
        }

        // ---- epilogue1: relu+bias -> h hi/lo into [0,64K); load W2 -> [64K,128K)
#pragma unroll
        for (int mi = 0; mi < 2; mi++) {
#pragma unroll
            for (int half = 0; half < 2; half++) {
                int rl = wm * 32 + mi * 16 + g + half * 8;
#pragma unroll
                for (int n8 = 0; n8 < 8; n8++) {
                    int cidx = wn * 64 + n8 * 8 + tig * 2;
                    float x0 = fmaxf(acc[mi][n8][half * 2 + 0] + __ldg(bias1 + cidx), 0.f);
                    float x1 = fmaxf(acc[mi][n8][half * 2 + 1] + __ldg(bias1 + cidx + 1), 0.f);
                    uint32_t hh, ll;
                    split2(x0, x1, hh, ll);
                    uint32_t off = (uint32_t)(rl * 128 + ((n8 ^ (rl & 7)) << 4) + tig * 4);
                    *(uint32_t*)(smem + wn * 32768 + off)         = hh;
                    *(uint32_t*)(smem + wn * 32768 + 16384 + off) = ll;
                }
            }
        }
#pragma unroll
        for (int i = 0; i < 8; i++) {
            int idx = i * 256 + tid;                 // 2048 chunks
            int k = idx >> 4, c = idx & 15;
            uint32_t off = (uint32_t)(k * 256 + ((c ^ (k & 7)) << 4));
            *(uint4*)(smem + SM_W2HI + off) =
                *(const uint4*)(g_w2_hi + (size_t)k * 128 + c * 8);
            *(uint4*)(smem + SM_W2LO + off) =
                *(const uint4*)(g_w2_lo + (size_t)k * 128 + c * 8);
        }
        __syncthreads();

        // ---- GEMM2: K=128, A = h smem (2 chunk bufs), B = W2 ----
#pragma unroll
        for (int mi = 0; mi < 2; mi++)
#pragma unroll
            for (int n8 = 0; n8 < 8; n8++)
#pragma unroll
                for (int q = 0; q < 4; q++) acc[mi][n8][q] = 0.f;

        for (int ch = 0; ch < 2; ch++) {
            uint32_t aHiB = sb + (uint32_t)(ch * 32768);
            uint32_t aLoB = aHiB + 16384;
#pragma unroll
            for (int kk = 0; kk < 4; kk++)
                mma_block(aHiB, aLoB, sb + SM_W2HI, sb + SM_W2LO, kk,
                          ch * 64 + kk * 16);
        }

        // ---- epilogue2: bias + mask select -> out ----
#pragma unroll
        for (int mi = 0; mi < 2; mi++) {
#pragma unroll
            for (int half = 0; half < 2; half++) {
                int r = rowBase + wm * 32 + mi * 16 + g + half * 8;
                bool doImp = (mask[r] != 0);
#pragma unroll
                for (int n8 = 0; n8 < 8; n8++) {
                    int cidx = wn * 64 + n8 * 8 + tig * 2;
                    float2 v;
                    v.x = acc[mi][n8][half * 2 + 0] + __ldg(bias2 + cidx);
                    v.y = acc[mi][n8][half * 2 + 1] + __ldg(bias2 + cidx + 1);
                    if (!doImp)
                        v = *(const float2*)(emb32 + (size_t)r * 128 + cidx);
                    *(float2*)(outp + (size_t)r * 128 + cidx) = v;
                }
            }
        }
        __syncthreads();   // protect smem before next tile's W1 load
    }
}

// ---------------- launch -------------------------------------------------------
extern "C" void kernel_launch(void* const* d_in, const int* in_sizes, int n_in,
                              void* d_out, int out_size) {
    const float* emb  = (const float*)d_in[0];
    const int*   mask = (const int*)d_in[1];
    const int*   edge = (const int*)d_in[2];
    const float* W1   = (const float*)d_in[3];
    const float* b1   = (const float*)d_in[4];
    const float* W2   = (const float*)d_in[5];
    const float* b2   = (const float*)d_in[6];
    float*       out  = (float*)d_out;

    cudaFuncSetAttribute(fused_k,
                         cudaFuncAttributeMaxDynamicSharedMemorySize, SMEM_FUSED);
    int dev = 0, sms = 148;
    cudaGetDevice(&dev);
    cudaDeviceGetAttribute(&sms, cudaDevAttrMultiProcessorCount, dev);
    if (sms > NTILES) sms = NTILES;

    // CSR build
    zero_counts_k<<<(NNODES + 255) / 256, 256>>>();
    hist_k<<<(NEDGES + 255) / 256, 256>>>(edge);
    scan_k<<<1, 1024>>>();
    scatter_k<<<(NEDGES + 255) / 256, 256>>>(edge);

    // fp16 embedding copy + weight splits
    econv16_k<<<NROWS * HDIM / (256 * 8), 256>>>(emb);
    __nv_bfloat16 *w1h, *w1l, *w2h, *w2l;
    cudaGetSymbolAddress((void**)&w1h, g_w1_hi);
    cudaGetSymbolAddress((void**)&w1l, g_w1_lo);
    cudaGetSymbolAddress((void**)&w2h, g_w2_hi);
    cudaGetSymbolAddress((void**)&w2l, g_w2_lo);
    wconv_k<<<128, 256>>>(W1, w1h, w1l, 256 * 128);
    wconv_k<<<64, 256>>>(W2, w2h, w2l, 128 * 128);

    // neighbor gather (fp16 reads, fp32 acc, bf16 hi/lo out)
    neighbor_k<<<NROWS / 8, 256>>>();

    // fused persistent GEMM1+GEMM2
    fused_k<<<sms, 256, SMEM_FUSED>>>(b1, b2, mask, emb, out);
}

// round 5
// speedup vs baseline: 2.0947x; 1.3883x over previous
#include <cuda_runtime.h>
#include <cuda_bf16.h>
#include <cuda_fp16.h>
#include <cstdint>

#define BATCH   16
#define NNODES  10000
#define HDIM    128
#define NEDGES  320000
#define NROWS   (BATCH * NNODES)      // 160000
#define NTILES  (NROWS / 128)         // 1250

// ---------------- scratch (device globals; no allocation allowed) ----------
__device__ int    g_counts[NNODES];
__device__ int    g_offsets[NNODES + 1];
__device__ int    g_cursor[NNODES];
__device__ int    g_csr[NEDGES];
__device__ __half g_emb16[(size_t)NROWS * HDIM];   // 41 MB fp16 copy
__device__ __half g_nbr16[(size_t)NROWS * HDIM];   // 41 MB neighbor sums
// weights native [K][N=128] row-major, fp16
__device__ __half g_w1_16[256 * 128];
__device__ __half g_w2_16[128 * 128];

// ---------------- helpers -----------------------------------------------------
__device__ __forceinline__ uint32_t smem_u32(const void* p) {
    uint32_t a;
    asm("{ .reg .u64 t; cvta.to.shared.u64 t, %1; cvt.u32.u64 %0, t; }"
        : "=r"(a) : "l"(p));
    return a;
}
__device__ __forceinline__ void ldsm4(uint32_t* r, uint32_t a) {
    asm volatile("ldmatrix.sync.aligned.m8n8.x4.shared.b16 {%0,%1,%2,%3}, [%4];"
                 : "=r"(r[0]), "=r"(r[1]), "=r"(r[2]), "=r"(r[3]) : "r"(a));
}
__device__ __forceinline__ void ldsm4t(uint32_t* r, uint32_t a) {
    asm volatile("ldmatrix.sync.aligned.m8n8.x4.trans.shared.b16 {%0,%1,%2,%3}, [%4];"
                 : "=r"(r[0]), "=r"(r[1]), "=r"(r[2]), "=r"(r[3]) : "r"(a));
}
__device__ __forceinline__ void mma16816(float* c, const uint32_t* a,
                                         uint32_t b0, uint32_t b1) {
    asm volatile(
        "mma.sync.aligned.m16n8k16.row.col.f32.f16.f16.f32 "
        "{%0,%1,%2,%3}, {%4,%5,%6,%7}, {%8,%9}, {%0,%1,%2,%3};"
        : "+f"(c[0]), "+f"(c[1]), "+f"(c[2]), "+f"(c[3])
        : "r"(a[0]), "r"(a[1]), "r"(a[2]), "r"(a[3]), "r"(b0), "r"(b1));
}

// ---------------- CSR build ----------------------------------------------------
__global__ void zero_counts_k() {
    int i = blockIdx.x * blockDim.x + threadIdx.x;
    if (i < NNODES) g_counts[i] = 0;
}
__global__ void hist_k(const int* __restrict__ edge) {
    int e = blockIdx.x * blockDim.x + threadIdx.x;
    if (e < NEDGES) atomicAdd(&g_counts[edge[NEDGES + e]], 1);
}
__global__ void scan_k() {
    __shared__ int part[1024];
    const int CH = 10;
    int t = threadIdx.x;
    int local[CH];
    int s = 0;
#pragma unroll
    for (int i = 0; i < CH; i++) {
        int idx = t * CH + i;
        int v = (idx < NNODES) ? g_counts[idx] : 0;
        local[i] = s;
        s += v;
    }
    part[t] = s;
    __syncthreads();
    for (int off = 1; off < 1024; off <<= 1) {
        int v = (t >= off) ? part[t - off] : 0;
        __syncthreads();
        part[t] += v;
        __syncthreads();
    }
    int excl = (t == 0) ? 0 : part[t - 1];
#pragma unroll
    for (int i = 0; i < CH; i++) {
        int idx = t * CH + i;
        if (idx < NNODES) {
            int o = excl + local[i];
            g_offsets[idx] = o;
            g_cursor[idx]  = o;
        }
    }
    if (t == 1023) g_offsets[NNODES] = part[1023];
}
__global__ void scatter_k(const int* __restrict__ edge) {
    int e = blockIdx.x * blockDim.x + threadIdx.x;
    if (e < NEDGES) {
        int d = edge[NEDGES + e];
        int p = atomicAdd(&g_cursor[d], 1);
        g_csr[p] = edge[e];
    }
}

// ---------------- emb fp32 -> fp16 copy ---------------------------------------
__global__ __launch_bounds__(256)
void econv16_k(const float* __restrict__ emb) {
    size_t i8 = (size_t)blockIdx.x * 256 + threadIdx.x;   // one 8-elt group
    const float4* s = (const float4*)(emb) + i8 * 2;
    float4 a = s[0], b = s[1];
    __half2 h0 = __float22half2_rn(make_float2(a.x, a.y));
    __half2 h1 = __float22half2_rn(make_float2(a.z, a.w));
    __half2 h2 = __float22half2_rn(make_float2(b.x, b.y));
    __half2 h3 = __float22half2_rn(make_float2(b.z, b.w));
    uint4 o;
    o.x = *(uint32_t*)&h0; o.y = *(uint32_t*)&h1;
    o.z = *(uint32_t*)&h2; o.w = *(uint32_t*)&h3;
    *((uint4*)g_emb16 + i8) = o;
}

// ---------------- neighbor gather-sum: fp16 reads, fp32 acc, fp16 out ---------
__global__ __launch_bounds__(256)
void neighbor_k() {
    int warp_global = blockIdx.x * 8 + (threadIdx.x >> 5);
    if (warp_global >= NROWS) return;
    int b = warp_global / NNODES;
    int n = warp_global - b * NNODES;
    int lane = threadIdx.x & 31;

    const __half* embB = g_emb16 + (size_t)b * NNODES * HDIM;
    int beg = g_offsets[n];
    int end = g_offsets[n + 1];

    float4 acc = make_float4(0.f, 0.f, 0.f, 0.f);
    int i = beg;
    for (; i + 4 <= end; i += 4) {
        int s0 = g_csr[i], s1 = g_csr[i + 1], s2 = g_csr[i + 2], s3 = g_csr[i + 3];
        uint2 p0 = *(const uint2*)(embB + (size_t)s0 * 128 + lane * 4);
        uint2 p1 = *(const uint2*)(embB + (size_t)s1 * 128 + lane * 4);
        uint2 p2 = *(const uint2*)(embB + (size_t)s2 * 128 + lane * 4);
        uint2 p3 = *(const uint2*)(embB + (size_t)s3 * 128 + lane * 4);
#pragma unroll
        for (int q = 0; q < 4; q++) {
            uint2 p = (q == 0) ? p0 : (q == 1) ? p1 : (q == 2) ? p2 : p3;
            float2 f0 = __half22float2(*(__half2*)&p.x);
            float2 f1 = __half22float2(*(__half2*)&p.y);
            acc.x += f0.x; acc.y += f0.y; acc.z += f1.x; acc.w += f1.y;
        }
    }
    for (; i < end; i++) {
        uint2 p = *(const uint2*)(embB + (size_t)g_csr[i] * 128 + lane * 4);
        float2 f0 = __half22float2(*(__half2*)&p.x);
        float2 f1 = __half22float2(*(__half2*)&p.y);
        acc.x += f0.x; acc.y += f0.y; acc.z += f1.x; acc.w += f1.y;
    }
    __half2 h0 = __floats2half2_rn(acc.x, acc.y);
    __half2 h1 = __floats2half2_rn(acc.z, acc.w);
    size_t o = (size_t)warp_global * 128 + lane * 4;
    *(uint2*)(g_nbr16 + o) = make_uint2(*(uint32_t*)&h0, *(uint32_t*)&h1);
}

// ---------------- weight fp32 -> fp16 (layout preserved [K][128]) -------------
__global__ void wconv_k(const float* __restrict__ W, __half* o16, int total) {
    int i = blockIdx.x * blockDim.x + threadIdx.x;
    if (i < total) o16[i] = __float2half_rn(W[i]);
}

// ---------------- fused GEMM1+GEMM2, persistent, single-pass fp16 -------------
// smem map (160KB dynamic):
//   [0, 64K)        W1 fp16 [256][128] swizzled      (loaded once)
//   [64K, 96K)      W2 fp16 [128][128] swizzled      (loaded once)
//   [96K, 128K)     h  fp16, 2 chunk-bufs of 16KB
//   [128K, 160K)    A staging: 2 bufs x 16KB
#define SM_W1    0
#define SM_W2    65536
#define SM_H     98304
#define SM_STAGE 131072
#define SMEM_FUSED 163840

__global__ __launch_bounds__(256, 1)
void fused_k(const float* __restrict__ bias1, const float* __restrict__ bias2,
             const int* __restrict__ mask, const float* __restrict__ emb32,
             float* __restrict__ outp) {
    extern __shared__ __align__(128) char smem[];
    int tid  = threadIdx.x;
    int lane = tid & 31;
    int wid  = tid >> 5;
    int wm   = wid & 3;
    int wn   = wid >> 2;
    int g    = lane >> 2, tig = lane & 3;
    uint32_t sb = smem_u32(smem);

    // ---- load W1 + W2 once, swizzled: off(k,c16)=k*256+((c^(k&7))<<4) ----
#pragma unroll
    for (int i = 0; i < 16; i++) {
        int idx = i * 256 + tid;                 // 4096 chunks
        int k = idx >> 4, c = idx & 15;
        uint32_t off = (uint32_t)(k * 256 + ((c ^ (k & 7)) << 4));
        *(uint4*)(smem + SM_W1 + off) =
            *(const uint4*)(g_w1_16 + (size_t)k * 128 + c * 8);
    }
#pragma unroll
    for (int i = 0; i < 8; i++) {
        int idx = i * 256 + tid;                 // 2048 chunks
        int k = idx >> 4, c = idx & 15;
        uint32_t off = (uint32_t)(k * 256 + ((c ^ (k & 7)) << 4));
        *(uint4*)(smem + SM_W2 + off) =
            *(const uint4*)(g_w2_16 + (size_t)k * 128 + c * 8);
    }
    __syncthreads();

    float acc[2][8][4];

    for (int tile = blockIdx.x; tile < NTILES; tile += gridDim.x) {
        int rowBase = tile * 128;

        // ---- A staging: chunk ch (64 fp16 cols) -> buf; pure 16B copies ----
        auto stage = [&](int ch, int buf) {
            char* dst = smem + SM_STAGE + buf * 16384;
            const __half* src = (ch < 2) ? g_nbr16 : g_emb16;
            int kb = (ch & 1) * 64;
#pragma unroll
            for (int it = 0; it < 4; it++) {
                int idx = it * 256 + tid;        // 1024 chunks
                int r = idx >> 3, c = idx & 7;
                uint32_t off = (uint32_t)(r * 128 + ((c ^ (r & 7)) << 4));
                *(uint4*)(dst + off) =
                    *(const uint4*)(src + (size_t)(rowBase + r) * 128 + kb + c * 8);
            }
        };

        // ---- single-pass MMA block: one 16-wide k slice ----
        auto mma_block = [&](uint32_t aB, uint32_t bB, int kk, int kAbs) {
            uint32_t aF[2][4], bF[4][4];
#pragma unroll
            for (int mi = 0; mi < 2; mi++) {
                int r = wm * 32 + mi * 16 + (lane & 15);
                int c = kk * 2 + (lane >> 4);
                uint32_t off = (uint32_t)(r * 128 + ((c ^ (r & 7)) << 4));
                ldsm4(aF[mi], aB + off);
            }
#pragma unroll
            for (int q = 0; q < 4; q++) {
                int k = kAbs + (lane & 15);
                int c = (wn * 64 + q * 16 + ((lane >> 4) << 3)) >> 3;
                uint32_t boff = (uint32_t)(k * 256 + ((c ^ (k & 7)) << 4));
                ldsm4t(bF[q], bB + boff);
            }
#pragma unroll
            for (int mi = 0; mi < 2; mi++)
#pragma unroll
                for (int n8 = 0; n8 < 8; n8++)
                    mma16816(acc[mi][n8], aF[mi],
                             bF[n8 >> 1][(n8 & 1) * 2], bF[n8 >> 1][(n8 & 1) * 2 + 1]);
        };

#pragma unroll
        for (int mi = 0; mi < 2; mi++)
#pragma unroll
            for (int n8 = 0; n8 < 8; n8++)
#pragma unroll
                for (int q = 0; q < 4; q++) acc[mi][n8][q] = 0.f;

        stage(0, 0);
        __syncthreads();

        // ---- GEMM1: K=256 in 4 chunks, double-buffered staging ----
        for (int ch = 0; ch < 4; ch++) {
            if (ch + 1 < 4) stage(ch + 1, (ch + 1) & 1);
            uint32_t aB = sb + SM_STAGE + (uint32_t)((ch & 1) * 16384);
#pragma unroll
            for (int kk = 0; kk < 4; kk++)
                mma_block(aB, sb + SM_W1, kk, ch * 64 + kk * 16);
            __syncthreads();
        }

        // ---- epilogue1: relu+bias -> h fp16 in smem ----
#pragma unroll
        for (int mi = 0; mi < 2; mi++) {
#pragma unroll
            for (int half = 0; half < 2; half++) {
                int rl = wm * 32 + mi * 16 + g + half * 8;
#pragma unroll
                for (int n8 = 0; n8 < 8; n8++) {
                    int cidx = wn * 64 + n8 * 8 + tig * 2;
                    float x0 = fmaxf(acc[mi][n8][half * 2 + 0] + __ldg(bias1 + cidx), 0.f);
                    float x1 = fmaxf(acc[mi][n8][half * 2 + 1] + __ldg(bias1 + cidx + 1), 0.f);
                    __half2 hv = __floats2half2_rn(x0, x1);
                    uint32_t off = (uint32_t)(rl * 128 + ((n8 ^ (rl & 7)) << 4) + tig * 4);
                    *(uint32_t*)(smem + SM_H + wn * 16384 + off) = *(uint32_t*)&hv;
                }
            }
        }
        __syncthreads();

        // ---- GEMM2: K=128, A = h smem (2 chunks), B = W2 ----
#pragma unroll
        for (int mi = 0; mi < 2; mi++)
#pragma unroll
            for (int n8 = 0; n8 < 8; n8++)
#pragma unroll
                for (int q = 0; q < 4; q++) acc[mi][n8][q] = 0.f;

#pragma unroll
        for (int ch = 0; ch < 2; ch++) {
            uint32_t aB = sb + SM_H + (uint32_t)(ch * 16384);
#pragma unroll
            for (int kk = 0; kk < 4; kk++)
                mma_block(aB, sb + SM_W2, kk, ch * 64 + kk * 16);
        }

        // ---- epilogue2: bias + mask select -> out ----
#pragma unroll
        for (int mi = 0; mi < 2; mi++) {
#pragma unroll
            for (int half = 0; half < 2; half++) {
                int r = rowBase + wm * 32 + mi * 16 + g + half * 8;
                bool doImp = (mask[r] != 0);
#pragma unroll
                for (int n8 = 0; n8 < 8; n8++) {
                    int cidx = wn * 64 + n8 * 8 + tig * 2;
                    float2 v;
                    v.x = acc[mi][n8][half * 2 + 0] + __ldg(bias2 + cidx);
                    v.y = acc[mi][n8][half * 2 + 1] + __ldg(bias2 + cidx + 1);
                    if (!doImp)
                        v = *(const float2*)(emb32 + (size_t)r * 128 + cidx);
                    *(float2*)(outp + (size_t)r * 128 + cidx) = v;
                }
            }
        }
        __syncthreads();   // protect h/stage smem before next tile
    }
}

// ---------------- launch -------------------------------------------------------
extern "C" void kernel_launch(void* const* d_in, const int* in_sizes, int n_in,
                              void* d_out, int out_size) {
    const float* emb  = (const float*)d_in[0];
    const int*   mask = (const int*)d_in[1];
    const int*   edge = (const int*)d_in[2];
    const float* W1   = (const float*)d_in[3];
    const float* b1   = (const float*)d_in[4];
    const float* W2   = (const float*)d_in[5];
    const float* b2   = (const float*)d_in[6];
    float*       out  = (float*)d_out;

    cudaFuncSetAttribute(fused_k,
                         cudaFuncAttributeMaxDynamicSharedMemorySize, SMEM_FUSED);
    int dev = 0, sms = 148;
    cudaGetDevice(&dev);
    cudaDeviceGetAttribute(&sms, cudaDevAttrMultiProcessorCount, dev);
    if (sms > NTILES) sms = NTILES;

    // CSR build
    zero_counts_k<<<(NNODES + 255) / 256, 256>>>();
    hist_k<<<(NEDGES + 255) / 256, 256>>>(edge);
    scan_k<<<1, 1024>>>();
    scatter_k<<<(NEDGES + 255) / 256, 256>>>(edge);

    // fp16 embedding copy + weight converts
    econv16_k<<<NROWS * HDIM / (256 * 8), 256>>>(emb);
    __half *w1p, *w2p;
    cudaGetSymbolAddress((void**)&w1p, g_w1_16);
    cudaGetSymbolAddress((void**)&w2p, g_w2_16);
    wconv_k<<<128, 256>>>(W1, w1p, 256 * 128);
    wconv_k<<<64, 256>>>(W2, w2p, 128 * 128);

    // neighbor gather (fp16 reads, fp32 acc, fp16 out)
    neighbor_k<<<NROWS / 8, 256>>>();

    // fused persistent GEMM1+GEMM2 (fp16 single-pass)
    fused_k<<<sms, 256, SMEM_FUSED>>>(b1, b2, mask, emb, out);
}